// round 12
// baseline (speedup 1.0000x reference)
#include <cuda_runtime.h>
#include <cuda_bf16.h>

// ---------------------------------------------------------------------------
// VoxelDistill: heatmap (centerpoint-style gaussian max, SCATTER form) +
// fused conv1x1 -> trilinear-downsample -> masked L1 distill loss.
//
// Algebra: all three lin_resize stages have weight exactly 0.5, so
// resize(conv(x)) == conv(avg8(x)). Average the 8 student taps per channel
// (d in {4D+1,4D+2}, h in {2H,2H+1}, w in {2W,2W+1}), then one 128x64
// matvec per output position.
//
// 3 graph nodes: memset(g_hm+sum) -> scatter heatmap (atomicMax + exact
// telescoping delta-sum, ONE atomicAdd per block) -> fused main.
// Main phase 2 is split into 2 passes of 8 channels with per-pass teacher
// prefetch so epilogue DRAM traffic overlaps the FMA loop.
// ---------------------------------------------------------------------------

#define EPS32F 1.1920928955078125e-7f
#define HM_CELLS (2 * 128 * 128)

__device__ float g_hm[HM_CELLS + 1];   // [D][H][W]; [HM_CELLS] = heatmap sum

__device__ __forceinline__ float gauss_radius(float h, float w) {
    const float ov = 0.1f;
    float b1 = h + w;
    float c1 = w * h * (1.0f - ov) / (1.0f + ov);
    float r1 = (b1 + sqrtf(fmaxf(b1 * b1 - 4.0f * c1, 0.0f))) / 2.0f;
    float b2 = 2.0f * (h + w);
    float c2 = (1.0f - ov) * w * h;
    float r2 = (b2 + sqrtf(fmaxf(b2 * b2 - 16.0f * c2, 0.0f))) / 2.0f;
    float b3 = -2.0f * ov * (h + w);
    float c3 = (ov - 1.0f) * w * h;
    float r3 = (b3 + sqrtf(fmaxf(b3 * b3 - 16.0f * ov * c3, 0.0f))) / 2.0f;
    return fminf(fminf(r1, r2), r3);
}

// One block per box; threads cover the (clipped) gaussian window.
// Sum deltas accumulate per-thread, block-reduce, ONE atomicAdd per block.
__global__ void __launch_bounds__(256)
vd_scatter_kernel(const float* __restrict__ boxes) {
    __shared__ float s_red[8];
    const float* B = boxes + blockIdx.x * 9;
    float bx = B[0], by = B[1], bz = B[2];
    float wf = B[3] / 0.1f / 8.0f;
    float lf = B[4] / 0.1f / 8.0f;
    float hf = B[5] / 0.2f / 8.0f;

    float r_xy = gauss_radius(lf, wf);
    float r_z  = fmaxf(gauss_radius(lf, hf), gauss_radius(wf, hf));
    int rx = max(2, (int)(r_xy / 0.4f));   // trunc toward zero, matches jnp
    int rz = max(2, (int)(r_z  / 1.0f));

    int cxi = (int)((bx + 51.2f) / 0.4f);
    int cyi = (int)((by + 51.2f) / 0.4f);
    int czi = (int)((bz + 5.0f)  / 1.0f);

    bool valid = (wf > 0.0f) && (lf > 0.0f) &&
                 (cxi >= 0) && (cxi < 128) &&
                 (cyi >= 0) && (cyi < 128) &&
                 (czi >= 0) && (czi <= 1);
    if (!valid) return;

    float sx = (2.0f * (float)rx + 1.0f) / 6.0f;
    float sz = (2.0f * (float)rz + 1.0f) / 6.0f;
    float dnx = 2.0f * sx * sx;            // sy == sx since ry == rx
    float dnz = 2.0f * sz * sz;

    int x0 = max(0, cxi - rx), x1 = min(127, cxi + rx);
    int y0 = max(0, cyi - rx), y1 = min(127, cyi + rx);
    int z0 = max(0, czi - rz), z1 = min(1,   czi + rz);
    int nx = x1 - x0 + 1, ny = y1 - y0 + 1, nz = z1 - z0 + 1;
    int nxy = nx * ny;
    int total = nxy * nz;

    float delta = 0.0f;
    for (int idx = threadIdx.x; idx < total; idx += 256) {
        int iz = idx / nxy;
        int r  = idx - iz * nxy;
        int iy = r / nx;
        int ix = r - iy * nx;
        int X = x0 + ix, Y = y0 + iy, Z = z0 + iz;
        int dx = X - cxi, dy = Y - cyi, dz = Z - czi;
        float e = (float)(dx * dx) / dnx
                + (float)(dy * dy) / dnx
                + (float)(dz * dz) / dnz;
        float g = expf(-e);
        if (g >= EPS32F) {
            int cell = Z * 16384 + X * 128 + Y;   // [D][H=x][W=y]
            int gi = __float_as_int(g);
            int old = atomicMax((int*)&g_hm[cell], gi);
            if (old < gi)   // deltas telescope to the per-cell max; additive
                delta += g - __int_as_float(old);
        }
    }

    int t = threadIdx.x;
    #pragma unroll
    for (int o = 16; o; o >>= 1) delta += __shfl_down_sync(0xffffffffu, delta, o);
    if ((t & 31) == 0) s_red[t >> 5] = delta;
    __syncthreads();
    if (t < 32) {
        float s = (t < 8) ? s_red[t] : 0.0f;
        #pragma unroll
        for (int o = 4; o; o >>= 1) s += __shfl_down_sync(0xffffffffu, s, o);
        if (t == 0) atomicAdd(&g_hm[HM_CELLS], s);
    }
}

// grid (2, 128, 2): block covers 64 output W at fixed (H, D). 256 threads.
// Lane l handles wi = 2l, 2l+1; warp og handles 16 channels in 2 passes of
// 8, each pass prefetching its teacher/bias before the FMA loop.
__global__ void __launch_bounds__(256, 3)
vd_main_kernel(const float* __restrict__ student,
               const float* __restrict__ teacher,
               const float* __restrict__ conv_w,
               const float* __restrict__ conv_b,
               float* __restrict__ out) {
    __shared__ float sh_w[128 * 64];        // conv_w [o][c], 32 KB
    __shared__ float sh_avg[64][64];        // avg8 student feats [c][wi], 16 KB

    int t  = threadIdx.x;
    int W0 = blockIdx.x * 64;
    int H  = blockIdx.y;
    int D  = blockIdx.z;

    // stage conv_w (float4)
    {
        const float4* w4p = (const float4*)conv_w;
        float4*       s4p = (float4*)sh_w;
        #pragma unroll
        for (int i = t; i < 2048; i += 256) s4p[i] = w4p[i];
    }

    // Phase 1: 8-tap average of student into shared (float4 loads).
    // student layout: c:524288, d:65536, h:256, w:1
    // task e: c = e>>5, pair p = e&31 -> outputs wi = 2p, 2p+1
    {
        int d0 = 4 * D + 1;
        int h0 = 2 * H;
        const float4* sp4 = (const float4*)student;
        #pragma unroll
        for (int i = 0; i < 8; i++) {
            int e = t + i * 256;
            int c = e >> 5;
            int p = e & 31;
            int fbase = c * 524288 + d0 * 65536 + h0 * 256 + 2 * W0 + 4 * p;
            int b4 = fbase >> 2;
            float4 q0 = sp4[b4];                    // d0,   h0
            float4 q1 = sp4[b4 + 64];               // d0,   h0+1
            float4 q2 = sp4[b4 + 16384];            // d0+1, h0
            float4 q3 = sp4[b4 + 16384 + 64];       // d0+1, h0+1
            float o0 = (q0.x + q0.y + q1.x + q1.y +
                        q2.x + q2.y + q3.x + q3.y) * 0.125f;
            float o1 = (q0.z + q0.w + q1.z + q1.w +
                        q2.z + q2.w + q3.z + q3.w) * 0.125f;
            *(float2*)&sh_avg[c][2 * p] = make_float2(o0, o1);
        }
    }

    // Epilogue constants (independent of sh_avg)
    int l  = t & 31;
    int og = t >> 5;
    float scale = 10.0f / (g_hm[HM_CELLS] + 1e-4f);
    int sp0 = D * 16384 + H * 128 + W0 + 2 * l;   // spatial index (D,H,W)
    float2 hm2 = *(const float2*)&g_hm[sp0];
    float f0 = hm2.x * scale;
    float f1 = hm2.y * scale;

    __syncthreads();

    // Phase 2: 2 passes of 8 channels; teacher/bias prefetched per pass so
    // the 16-iter FMA loop hides their DRAM latency and stores are spread.
    #pragma unroll
    for (int pass = 0; pass < 2; pass++) {
        int obase = og * 16 + pass * 8;

        float2 t2[8];
        float  bv[8];
        #pragma unroll
        for (int k = 0; k < 8; k++) {
            t2[k] = *(const float2*)&teacher[(obase + k) * 32768 + sp0];
            bv[k] = __ldg(&conv_b[obase + k]);
        }

        float acc0[8], acc1[8];
        #pragma unroll
        for (int k = 0; k < 8; k++) { acc0[k] = 0.0f; acc1[k] = 0.0f; }

        #pragma unroll
        for (int c4 = 0; c4 < 64; c4 += 4) {
            float2 va = *(const float2*)&sh_avg[c4 + 0][2 * l];
            float2 vb = *(const float2*)&sh_avg[c4 + 1][2 * l];
            float2 vc = *(const float2*)&sh_avg[c4 + 2][2 * l];
            float2 vd = *(const float2*)&sh_avg[c4 + 3][2 * l];
            #pragma unroll
            for (int k = 0; k < 8; k++) {
                const float4 w4 = *(const float4*)&sh_w[(obase + k) * 64 + c4];
                acc0[k] += w4.x * va.x + w4.y * vb.x + w4.z * vc.x + w4.w * vd.x;
                acc1[k] += w4.x * va.y + w4.y * vb.y + w4.z * vc.y + w4.w * vd.y;
            }
        }

        // loss = |conv + b - teacher| * hm * 10 / (sum + 1e-4)
        #pragma unroll
        for (int k = 0; k < 8; k++) {
            int idx = (obase + k) * 32768 + sp0;
            float2 r;
            r.x = fabsf(acc0[k] + bv[k] - t2[k].x) * f0;
            r.y = fabsf(acc1[k] + bv[k] - t2[k].y) * f1;
            *(float2*)&out[idx] = r;
        }
    }
}

extern "C" void kernel_launch(void* const* d_in, const int* in_sizes, int n_in,
                              void* d_out, int out_size) {
    const float* boxes   = (const float*)d_in[0];
    // d_in[1] = gt_labels_3d (unused by reference)
    const float* teacher = (const float*)d_in[2];
    const float* student = (const float*)d_in[3];
    const float* conv_w  = (const float*)d_in[4];
    const float* conv_b  = (const float*)d_in[5];
    int N = in_sizes[0] / 9;

    void* hm_ptr = nullptr;
    cudaGetSymbolAddress(&hm_ptr, g_hm);
    cudaMemsetAsync(hm_ptr, 0, (HM_CELLS + 1) * sizeof(float), 0);

    if (N > 0) vd_scatter_kernel<<<N, 256>>>(boxes);

    dim3 grid(2, 128, 2);
    vd_main_kernel<<<grid, 256>>>(student, teacher, conv_w, conv_b,
                                  (float*)d_out);
}

// round 13
// speedup vs baseline: 1.9745x; 1.9745x over previous
#include <cuda_runtime.h>
#include <cuda_bf16.h>

// ---------------------------------------------------------------------------
// VoxelDistill: heatmap (centerpoint-style gaussian max, SCATTER form) +
// fused conv1x1 -> trilinear-downsample -> masked L1 distill loss.
//
// Algebra: all three lin_resize stages have weight exactly 0.5, so
// resize(conv(x)) == conv(avg8(x)). Average the 8 student taps per channel
// (d in {4D+1,4D+2}, h in {2H,2H+1}, w in {2W,2W+1}), then one 128x64
// matvec per output position.
//
// 3 graph nodes: memset(g_hm+sum) -> scatter heatmap (atomicMax + exact
// telescoping delta-sum, ONE atomicAdd per block) -> fused main.
// Main kernel is the R7-measured form (29.0 us) verbatim.
// ---------------------------------------------------------------------------

#define EPS32F 1.1920928955078125e-7f
#define HM_CELLS (2 * 128 * 128)

__device__ float g_hm[HM_CELLS + 1];   // [D][H][W]; [HM_CELLS] = heatmap sum

__device__ __forceinline__ float gauss_radius(float h, float w) {
    const float ov = 0.1f;
    float b1 = h + w;
    float c1 = w * h * (1.0f - ov) / (1.0f + ov);
    float r1 = (b1 + sqrtf(fmaxf(b1 * b1 - 4.0f * c1, 0.0f))) / 2.0f;
    float b2 = 2.0f * (h + w);
    float c2 = (1.0f - ov) * w * h;
    float r2 = (b2 + sqrtf(fmaxf(b2 * b2 - 16.0f * c2, 0.0f))) / 2.0f;
    float b3 = -2.0f * ov * (h + w);
    float c3 = (ov - 1.0f) * w * h;
    float r3 = (b3 + sqrtf(fmaxf(b3 * b3 - 16.0f * ov * c3, 0.0f))) / 2.0f;
    return fminf(fminf(r1, r2), r3);
}

// One block per box; threads cover the (clipped) gaussian window.
// Sum deltas accumulate per-thread, block-reduce, ONE atomicAdd per block.
__global__ void __launch_bounds__(256)
vd_scatter_kernel(const float* __restrict__ boxes) {
    __shared__ float s_red[8];
    const float* B = boxes + blockIdx.x * 9;
    float bx = B[0], by = B[1], bz = B[2];
    float wf = B[3] / 0.1f / 8.0f;
    float lf = B[4] / 0.1f / 8.0f;
    float hf = B[5] / 0.2f / 8.0f;

    float r_xy = gauss_radius(lf, wf);
    float r_z  = fmaxf(gauss_radius(lf, hf), gauss_radius(wf, hf));
    int rx = max(2, (int)(r_xy / 0.4f));   // trunc toward zero, matches jnp
    int rz = max(2, (int)(r_z  / 1.0f));

    int cxi = (int)((bx + 51.2f) / 0.4f);
    int cyi = (int)((by + 51.2f) / 0.4f);
    int czi = (int)((bz + 5.0f)  / 1.0f);

    bool valid = (wf > 0.0f) && (lf > 0.0f) &&
                 (cxi >= 0) && (cxi < 128) &&
                 (cyi >= 0) && (cyi < 128) &&
                 (czi >= 0) && (czi <= 1);
    if (!valid) return;

    float sx = (2.0f * (float)rx + 1.0f) / 6.0f;
    float sz = (2.0f * (float)rz + 1.0f) / 6.0f;
    float dnx = 2.0f * sx * sx;            // sy == sx since ry == rx
    float dnz = 2.0f * sz * sz;

    int x0 = max(0, cxi - rx), x1 = min(127, cxi + rx);
    int y0 = max(0, cyi - rx), y1 = min(127, cyi + rx);
    int z0 = max(0, czi - rz), z1 = min(1,   czi + rz);
    int nx = x1 - x0 + 1, ny = y1 - y0 + 1, nz = z1 - z0 + 1;
    int nxy = nx * ny;
    int total = nxy * nz;

    float delta = 0.0f;
    for (int idx = threadIdx.x; idx < total; idx += 256) {
        int iz = idx / nxy;
        int r  = idx - iz * nxy;
        int iy = r / nx;
        int ix = r - iy * nx;
        int X = x0 + ix, Y = y0 + iy, Z = z0 + iz;
        int dx = X - cxi, dy = Y - cyi, dz = Z - czi;
        float e = (float)(dx * dx) / dnx
                + (float)(dy * dy) / dnx
                + (float)(dz * dz) / dnz;
        float g = expf(-e);
        if (g >= EPS32F) {
            int cell = Z * 16384 + X * 128 + Y;   // [D][H=x][W=y]
            int gi = __float_as_int(g);
            int old = atomicMax((int*)&g_hm[cell], gi);
            if (old < gi)   // deltas telescope to the per-cell max; additive
                delta += g - __int_as_float(old);
        }
    }

    int t = threadIdx.x;
    #pragma unroll
    for (int o = 16; o; o >>= 1) delta += __shfl_down_sync(0xffffffffu, delta, o);
    if ((t & 31) == 0) s_red[t >> 5] = delta;
    __syncthreads();
    if (t < 32) {
        float s = (t < 8) ? s_red[t] : 0.0f;
        #pragma unroll
        for (int o = 4; o; o >>= 1) s += __shfl_down_sync(0xffffffffu, s, o);
        if (t == 0) atomicAdd(&g_hm[HM_CELLS], s);
    }
}

// grid (2, 128, 2): block covers 64 output W at fixed (H, D). 256 threads.
// Each thread: 16 output channels x 2 adjacent W positions.  (R7 verbatim.)
__global__ void __launch_bounds__(256, 3)
vd_main_kernel(const float* __restrict__ student,
               const float* __restrict__ teacher,
               const float* __restrict__ conv_w,
               const float* __restrict__ conv_b,
               float* __restrict__ out) {
    __shared__ float sh_w[128 * 64];        // conv_w [o][c], 32 KB
    __shared__ float sh_avg[64][64];        // avg8 student feats [c][wi], 16 KB
    __shared__ float sh_b[128];

    int t  = threadIdx.x;
    int W0 = blockIdx.x * 64;
    int H  = blockIdx.y;
    int D  = blockIdx.z;

    // stage conv_w (float4) + conv_b
    {
        const float4* w4p = (const float4*)conv_w;
        float4*       s4p = (float4*)sh_w;
        #pragma unroll
        for (int i = t; i < 2048; i += 256) s4p[i] = w4p[i];
        if (t < 128) sh_b[t] = conv_b[t];
    }

    // heatmap scale factor (scatter kernel left sum at g_hm[HM_CELLS])
    float scale = 10.0f / (g_hm[HM_CELLS] + 1e-4f);

    // Phase 1: 8-tap average of student into shared (float4 loads).
    // student layout: c:524288, d:65536, h:256, w:1
    // task e: c = e>>5, pair p = e&31 -> outputs wi = 2p, 2p+1
    {
        int d0 = 4 * D + 1;
        int h0 = 2 * H;
        const float4* sp4 = (const float4*)student;
        #pragma unroll
        for (int i = 0; i < 8; i++) {
            int e = t + i * 256;
            int c = e >> 5;
            int p = e & 31;
            int fbase = c * 524288 + d0 * 65536 + h0 * 256 + 2 * W0 + 4 * p;
            int b4 = fbase >> 2;
            float4 q0 = sp4[b4];                    // d0, h0
            float4 q1 = sp4[b4 + 64];               // d0, h0+1
            float4 q2 = sp4[b4 + 16384];            // d0+1, h0
            float4 q3 = sp4[b4 + 16384 + 64];       // d0+1, h0+1
            float o0 = (q0.x + q0.y + q1.x + q1.y +
                        q2.x + q2.y + q3.x + q3.y) * 0.125f;
            float o1 = (q0.z + q0.w + q1.z + q1.w +
                        q2.z + q2.w + q3.z + q3.w) * 0.125f;
            *(float2*)&sh_avg[c][2 * p] = make_float2(o0, o1);
        }
    }
    __syncthreads();

    // Phase 2: lane l handles wi = 2l, 2l+1; warp og handles 16 channels.
    int l  = t & 31;
    int og = t >> 5;
    float acc0[16], acc1[16];
    #pragma unroll
    for (int k = 0; k < 16; k++) { acc0[k] = 0.0f; acc1[k] = 0.0f; }

    #pragma unroll
    for (int c4 = 0; c4 < 64; c4 += 4) {
        float2 va = *(const float2*)&sh_avg[c4 + 0][2 * l];
        float2 vb = *(const float2*)&sh_avg[c4 + 1][2 * l];
        float2 vc = *(const float2*)&sh_avg[c4 + 2][2 * l];
        float2 vd = *(const float2*)&sh_avg[c4 + 3][2 * l];
        #pragma unroll
        for (int k = 0; k < 16; k++) {
            const float4 w4 = *(const float4*)&sh_w[(og * 16 + k) * 64 + c4];
            acc0[k] += w4.x * va.x + w4.y * vb.x + w4.z * vc.x + w4.w * vd.x;
            acc1[k] += w4.x * va.y + w4.y * vb.y + w4.z * vc.y + w4.w * vd.y;
        }
    }

    // Epilogue: loss = |conv + b - teacher| * hm * 10 / (sum + 1e-4)
    int sp0 = D * 16384 + H * 128 + W0 + 2 * l;   // spatial index (D,H,W)
    float2 hm2 = *(const float2*)&g_hm[sp0];
    float f0 = hm2.x * scale;
    float f1 = hm2.y * scale;

    #pragma unroll
    for (int k = 0; k < 16; k++) {
        int o   = og * 16 + k;
        int idx = o * 32768 + sp0;
        float2 t2 = *(const float2*)&teacher[idx];
        float  bk = sh_b[o];
        float2 r;
        r.x = fabsf(acc0[k] + bk - t2.x) * f0;
        r.y = fabsf(acc1[k] + bk - t2.y) * f1;
        *(float2*)&out[idx] = r;
    }
}

extern "C" void kernel_launch(void* const* d_in, const int* in_sizes, int n_in,
                              void* d_out, int out_size) {
    const float* boxes   = (const float*)d_in[0];
    // d_in[1] = gt_labels_3d (unused by reference)
    const float* teacher = (const float*)d_in[2];
    const float* student = (const float*)d_in[3];
    const float* conv_w  = (const float*)d_in[4];
    const float* conv_b  = (const float*)d_in[5];
    int N = in_sizes[0] / 9;

    void* hm_ptr = nullptr;
    cudaGetSymbolAddress(&hm_ptr, g_hm);
    cudaMemsetAsync(hm_ptr, 0, (HM_CELLS + 1) * sizeof(float), 0);

    if (N > 0) vd_scatter_kernel<<<N, 256>>>(boxes);

    dim3 grid(2, 128, 2);
    vd_main_kernel<<<grid, 256>>>(student, teacher, conv_w, conv_b,
                                  (float*)d_out);
}

// round 14
// speedup vs baseline: 2.1034x; 1.0653x over previous
#include <cuda_runtime.h>
#include <cuda_bf16.h>

// ---------------------------------------------------------------------------
// VoxelDistill: heatmap (centerpoint-style gaussian max, SCATTER form) +
// fused conv1x1 -> trilinear-downsample -> masked L1 distill loss.
//
// Algebra: all three lin_resize stages have weight exactly 0.5, so
// resize(conv(x)) == conv(avg8(x)). Average the 8 student taps per channel
// (d in {4D+1,4D+2}, h in {2H,2H+1}, w in {2W,2W+1}), then one 128x64
// matvec per output position.
//
// 2 graph nodes only: scatter heatmap -> fused main. No memset node:
// __device__ globals start zeroed; the main kernel self-cleans g_hm (each
// block zeroes its own cells after all its warps consumed them) and the
// heatmap sum (last-block-out counter), restoring the zero invariant for
// the next graph replay.
// ---------------------------------------------------------------------------

#define EPS32F 1.1920928955078125e-7f
#define HM_CELLS (2 * 128 * 128)

__device__ float g_hm[HM_CELLS + 1];   // [D][H][W]; [HM_CELLS] = heatmap sum
__device__ int   g_done;               // main-kernel block completion counter

__device__ __forceinline__ float gauss_radius(float h, float w) {
    const float ov = 0.1f;
    float b1 = h + w;
    float c1 = w * h * (1.0f - ov) / (1.0f + ov);
    float r1 = (b1 + sqrtf(fmaxf(b1 * b1 - 4.0f * c1, 0.0f))) / 2.0f;
    float b2 = 2.0f * (h + w);
    float c2 = (1.0f - ov) * w * h;
    float r2 = (b2 + sqrtf(fmaxf(b2 * b2 - 16.0f * c2, 0.0f))) / 2.0f;
    float b3 = -2.0f * ov * (h + w);
    float c3 = (ov - 1.0f) * w * h;
    float r3 = (b3 + sqrtf(fmaxf(b3 * b3 - 16.0f * ov * c3, 0.0f))) / 2.0f;
    return fminf(fminf(r1, r2), r3);
}

// One block per box; threads cover the (clipped) gaussian window.
// Sum deltas accumulate per-thread, block-reduce, ONE atomicAdd per block.
__global__ void __launch_bounds__(256)
vd_scatter_kernel(const float* __restrict__ boxes) {
    __shared__ float s_red[8];
    const float* B = boxes + blockIdx.x * 9;
    float bx = B[0], by = B[1], bz = B[2];
    float wf = B[3] / 0.1f / 8.0f;
    float lf = B[4] / 0.1f / 8.0f;
    float hf = B[5] / 0.2f / 8.0f;

    float r_xy = gauss_radius(lf, wf);
    float r_z  = fmaxf(gauss_radius(lf, hf), gauss_radius(wf, hf));
    int rx = max(2, (int)(r_xy / 0.4f));   // trunc toward zero, matches jnp
    int rz = max(2, (int)(r_z  / 1.0f));

    int cxi = (int)((bx + 51.2f) / 0.4f);
    int cyi = (int)((by + 51.2f) / 0.4f);
    int czi = (int)((bz + 5.0f)  / 1.0f);

    bool valid = (wf > 0.0f) && (lf > 0.0f) &&
                 (cxi >= 0) && (cxi < 128) &&
                 (cyi >= 0) && (cyi < 128) &&
                 (czi >= 0) && (czi <= 1);
    if (!valid) return;

    float sx = (2.0f * (float)rx + 1.0f) / 6.0f;
    float sz = (2.0f * (float)rz + 1.0f) / 6.0f;
    float dnx = 2.0f * sx * sx;            // sy == sx since ry == rx
    float dnz = 2.0f * sz * sz;

    int x0 = max(0, cxi - rx), x1 = min(127, cxi + rx);
    int y0 = max(0, cyi - rx), y1 = min(127, cyi + rx);
    int z0 = max(0, czi - rz), z1 = min(1,   czi + rz);
    int nx = x1 - x0 + 1, ny = y1 - y0 + 1, nz = z1 - z0 + 1;
    int nxy = nx * ny;
    int total = nxy * nz;

    float delta = 0.0f;
    for (int idx = threadIdx.x; idx < total; idx += 256) {
        int iz = idx / nxy;
        int r  = idx - iz * nxy;
        int iy = r / nx;
        int ix = r - iy * nx;
        int X = x0 + ix, Y = y0 + iy, Z = z0 + iz;
        int dx = X - cxi, dy = Y - cyi, dz = Z - czi;
        float e = (float)(dx * dx) / dnx
                + (float)(dy * dy) / dnx
                + (float)(dz * dz) / dnz;
        float g = expf(-e);
        if (g >= EPS32F) {
            int cell = Z * 16384 + X * 128 + Y;   // [D][H=x][W=y]
            int gi = __float_as_int(g);
            int old = atomicMax((int*)&g_hm[cell], gi);
            if (old < gi)   // deltas telescope to the per-cell max; additive
                delta += g - __int_as_float(old);
        }
    }

    int t = threadIdx.x;
    #pragma unroll
    for (int o = 16; o; o >>= 1) delta += __shfl_down_sync(0xffffffffu, delta, o);
    if ((t & 31) == 0) s_red[t >> 5] = delta;
    __syncthreads();
    if (t < 32) {
        float s = (t < 8) ? s_red[t] : 0.0f;
        #pragma unroll
        for (int o = 4; o; o >>= 1) s += __shfl_down_sync(0xffffffffu, s, o);
        if (t == 0) atomicAdd(&g_hm[HM_CELLS], s);
    }
}

// grid (2, 128, 2): block covers 64 output W at fixed (H, D). 256 threads.
// Each thread: 16 output channels x 2 adjacent W positions.
// Self-cleaning: after every warp in the block has consumed its hm values,
// warp 0 zeroes the block's 128 cells; the last block to finish reading the
// sum zeroes it (counter protocol) so the next replay starts from zero.
__global__ void __launch_bounds__(256, 3)
vd_main_kernel(const float* __restrict__ student,
               const float* __restrict__ teacher,
               const float* __restrict__ conv_w,
               const float* __restrict__ conv_b,
               float* __restrict__ out) {
    __shared__ float sh_w[128 * 64];        // conv_w [o][c], 32 KB
    __shared__ float sh_avg[64][64];        // avg8 student feats [c][wi], 16 KB
    __shared__ float sh_b[128];
    __shared__ float s_sum;

    int t  = threadIdx.x;
    int W0 = blockIdx.x * 64;
    int H  = blockIdx.y;
    int D  = blockIdx.z;

    // stage conv_w (float4) + conv_b + heatmap sum (staged through shared so
    // the global load is provably complete before the counter increment)
    {
        const float4* w4p = (const float4*)conv_w;
        float4*       s4p = (float4*)sh_w;
        #pragma unroll
        for (int i = t; i < 2048; i += 256) s4p[i] = w4p[i];
        if (t < 128) sh_b[t] = conv_b[t];
        if (t == 0) s_sum = g_hm[HM_CELLS];
    }

    // Phase 1: 8-tap average of student into shared (float4 loads).
    // student layout: c:524288, d:65536, h:256, w:1
    // task e: c = e>>5, pair p = e&31 -> outputs wi = 2p, 2p+1
    {
        int d0 = 4 * D + 1;
        int h0 = 2 * H;
        const float4* sp4 = (const float4*)student;
        #pragma unroll
        for (int i = 0; i < 8; i++) {
            int e = t + i * 256;
            int c = e >> 5;
            int p = e & 31;
            int fbase = c * 524288 + d0 * 65536 + h0 * 256 + 2 * W0 + 4 * p;
            int b4 = fbase >> 2;
            float4 q0 = sp4[b4];                    // d0, h0
            float4 q1 = sp4[b4 + 64];               // d0, h0+1
            float4 q2 = sp4[b4 + 16384];            // d0+1, h0
            float4 q3 = sp4[b4 + 16384 + 64];       // d0+1, h0+1
            float o0 = (q0.x + q0.y + q1.x + q1.y +
                        q2.x + q2.y + q3.x + q3.y) * 0.125f;
            float o1 = (q0.z + q0.w + q1.z + q1.w +
                        q2.z + q2.w + q3.z + q3.w) * 0.125f;
            *(float2*)&sh_avg[c][2 * p] = make_float2(o0, o1);
        }
    }
    __syncthreads();

    int l  = t & 31;
    int og = t >> 5;
    int sp0 = D * 16384 + H * 128 + W0 + 2 * l;   // spatial index (D,H,W)

    // Read + consume hm values (FMUL forces the loads complete), then
    // barrier, then warp 0 may safely zero the block's cells.
    float scale = 10.0f / (s_sum + 1e-4f);
    float2 hm2 = *(const float2*)&g_hm[sp0];
    float f0 = hm2.x * scale;
    float f1 = hm2.y * scale;
    __syncthreads();

    if (og == 0)
        *(float2*)&g_hm[sp0] = make_float2(0.0f, 0.0f);
    if (t == 0) {
        int old = atomicAdd(&g_done, 1);
        if (old == (int)(gridDim.x * gridDim.y * gridDim.z) - 1) {
            g_hm[HM_CELLS] = 0.0f;   // all blocks have read the sum
            g_done = 0;
        }
    }

    // Phase 2: lane l handles wi = 2l, 2l+1; warp og handles 16 channels.
    float acc0[16], acc1[16];
    #pragma unroll
    for (int k = 0; k < 16; k++) { acc0[k] = 0.0f; acc1[k] = 0.0f; }

    #pragma unroll
    for (int c4 = 0; c4 < 64; c4 += 4) {
        float2 va = *(const float2*)&sh_avg[c4 + 0][2 * l];
        float2 vb = *(const float2*)&sh_avg[c4 + 1][2 * l];
        float2 vc = *(const float2*)&sh_avg[c4 + 2][2 * l];
        float2 vd = *(const float2*)&sh_avg[c4 + 3][2 * l];
        #pragma unroll
        for (int k = 0; k < 16; k++) {
            const float4 w4 = *(const float4*)&sh_w[(og * 16 + k) * 64 + c4];
            acc0[k] += w4.x * va.x + w4.y * vb.x + w4.z * vc.x + w4.w * vd.x;
            acc1[k] += w4.x * va.y + w4.y * vb.y + w4.z * vc.y + w4.w * vd.y;
        }
    }

    // Epilogue: loss = |conv + b - teacher| * hm * 10 / (sum + 1e-4)
    #pragma unroll
    for (int k = 0; k < 16; k++) {
        int o   = og * 16 + k;
        int idx = o * 32768 + sp0;
        float2 t2 = *(const float2*)&teacher[idx];
        float  bk = sh_b[o];
        float2 r;
        r.x = fabsf(acc0[k] + bk - t2.x) * f0;
        r.y = fabsf(acc1[k] + bk - t2.y) * f1;
        *(float2*)&out[idx] = r;
    }
}

extern "C" void kernel_launch(void* const* d_in, const int* in_sizes, int n_in,
                              void* d_out, int out_size) {
    const float* boxes   = (const float*)d_in[0];
    // d_in[1] = gt_labels_3d (unused by reference)
    const float* teacher = (const float*)d_in[2];
    const float* student = (const float*)d_in[3];
    const float* conv_w  = (const float*)d_in[4];
    const float* conv_b  = (const float*)d_in[5];
    int N = in_sizes[0] / 9;

    if (N > 0) vd_scatter_kernel<<<N, 256>>>(boxes);

    dim3 grid(2, 128, 2);
    vd_main_kernel<<<grid, 256>>>(student, teacher, conv_w, conv_b,
                                  (float*)d_out);
}

// round 15
// speedup vs baseline: 2.2329x; 1.0616x over previous
#include <cuda_runtime.h>
#include <cuda_bf16.h>

// ---------------------------------------------------------------------------
// VoxelDistill: heatmap (centerpoint-style gaussian max, SCATTER form) +
// fused conv1x1 -> trilinear-downsample -> masked L1 distill loss.
//
// Algebra: all three lin_resize stages have weight exactly 0.5, so
// resize(conv(x)) == conv(avg8(x)). Average the 8 student taps per channel
// (d in {4D+1,4D+2}, h in {2H,2H+1}, w in {2W,2W+1}), then one 128x64
// matvec per output position.
//
// 2 graph nodes: scatter heatmap -> fused main (self-cleaning state).
// Main double-buffers the channel dimension: half-1's global loads are
// issued into registers BEFORE the half-0 FMA block, overlapping DRAM
// with compute inside each CTA.
// ---------------------------------------------------------------------------

#define EPS32F 1.1920928955078125e-7f
#define HM_CELLS (2 * 128 * 128)

__device__ float g_hm[HM_CELLS + 1];   // [D][H][W]; [HM_CELLS] = heatmap sum
__device__ int   g_done;               // main-kernel block completion counter

__device__ __forceinline__ float gauss_radius(float h, float w) {
    const float ov = 0.1f;
    float b1 = h + w;
    float c1 = w * h * (1.0f - ov) / (1.0f + ov);
    float r1 = (b1 + sqrtf(fmaxf(b1 * b1 - 4.0f * c1, 0.0f))) / 2.0f;
    float b2 = 2.0f * (h + w);
    float c2 = (1.0f - ov) * w * h;
    float r2 = (b2 + sqrtf(fmaxf(b2 * b2 - 16.0f * c2, 0.0f))) / 2.0f;
    float b3 = -2.0f * ov * (h + w);
    float c3 = (ov - 1.0f) * w * h;
    float r3 = (b3 + sqrtf(fmaxf(b3 * b3 - 16.0f * ov * c3, 0.0f))) / 2.0f;
    return fminf(fminf(r1, r2), r3);
}

// One block per box; threads cover the (clipped) gaussian window.
__global__ void __launch_bounds__(256)
vd_scatter_kernel(const float* __restrict__ boxes) {
    __shared__ float s_red[8];
    const float* B = boxes + blockIdx.x * 9;
    float bx = B[0], by = B[1], bz = B[2];
    float wf = B[3] / 0.1f / 8.0f;
    float lf = B[4] / 0.1f / 8.0f;
    float hf = B[5] / 0.2f / 8.0f;

    float r_xy = gauss_radius(lf, wf);
    float r_z  = fmaxf(gauss_radius(lf, hf), gauss_radius(wf, hf));
    int rx = max(2, (int)(r_xy / 0.4f));   // trunc toward zero, matches jnp
    int rz = max(2, (int)(r_z  / 1.0f));

    int cxi = (int)((bx + 51.2f) / 0.4f);
    int cyi = (int)((by + 51.2f) / 0.4f);
    int czi = (int)((bz + 5.0f)  / 1.0f);

    bool valid = (wf > 0.0f) && (lf > 0.0f) &&
                 (cxi >= 0) && (cxi < 128) &&
                 (cyi >= 0) && (cyi < 128) &&
                 (czi >= 0) && (czi <= 1);
    if (!valid) return;

    float sx = (2.0f * (float)rx + 1.0f) / 6.0f;
    float sz = (2.0f * (float)rz + 1.0f) / 6.0f;
    float dnx = 2.0f * sx * sx;            // sy == sx since ry == rx
    float dnz = 2.0f * sz * sz;

    int x0 = max(0, cxi - rx), x1 = min(127, cxi + rx);
    int y0 = max(0, cyi - rx), y1 = min(127, cyi + rx);
    int z0 = max(0, czi - rz), z1 = min(1,   czi + rz);
    int nx = x1 - x0 + 1, ny = y1 - y0 + 1, nz = z1 - z0 + 1;
    int nxy = nx * ny;
    int total = nxy * nz;

    float delta = 0.0f;
    for (int idx = threadIdx.x; idx < total; idx += 256) {
        int iz = idx / nxy;
        int r  = idx - iz * nxy;
        int iy = r / nx;
        int ix = r - iy * nx;
        int X = x0 + ix, Y = y0 + iy, Z = z0 + iz;
        int dx = X - cxi, dy = Y - cyi, dz = Z - czi;
        float e = (float)(dx * dx) / dnx
                + (float)(dy * dy) / dnx
                + (float)(dz * dz) / dnz;
        float g = expf(-e);
        if (g >= EPS32F) {
            int cell = Z * 16384 + X * 128 + Y;   // [D][H=x][W=y]
            int gi = __float_as_int(g);
            int old = atomicMax((int*)&g_hm[cell], gi);
            if (old < gi)   // deltas telescope to the per-cell max; additive
                delta += g - __int_as_float(old);
        }
    }

    int t = threadIdx.x;
    #pragma unroll
    for (int o = 16; o; o >>= 1) delta += __shfl_down_sync(0xffffffffu, delta, o);
    if ((t & 31) == 0) s_red[t >> 5] = delta;
    __syncthreads();
    if (t < 32) {
        float s = (t < 8) ? s_red[t] : 0.0f;
        #pragma unroll
        for (int o = 4; o; o >>= 1) s += __shfl_down_sync(0xffffffffu, s, o);
        if (t == 0) atomicAdd(&g_hm[HM_CELLS], s);
    }
}

// grid (2, 128, 2): block covers 64 output W at fixed (H, D). 256 threads.
// Channel dim split into halves of 32; half-1 LDGs issue before half-0's
// FMA block so DRAM overlaps compute. Inner loop shape identical to the
// proven R7 form.
__global__ void __launch_bounds__(256, 2)
vd_main_kernel(const float* __restrict__ student,
               const float* __restrict__ teacher,
               const float* __restrict__ conv_w,
               const float* __restrict__ conv_b,
               float* __restrict__ out) {
    __shared__ float sh_w[128 * 64];         // conv_w [o][c], 32 KB
    __shared__ float sh_avg[2][32][64];      // [half][c][wi], 16 KB
    __shared__ float sh_b[128];
    __shared__ float s_sum;

    int t  = threadIdx.x;
    int W0 = blockIdx.x * 64;
    int H  = blockIdx.y;
    int D  = blockIdx.z;

    int d0 = 4 * D + 1;
    int h0 = 2 * H;
    const float4* sp4 = (const float4*)student;

    // task decomposition (per half): e = t + i*256, i in 0..3
    //   c_local = e>>5 (0..31), pair p = e&31 -> wi = 2p, 2p+1
    int cl[4], pp[4];
    #pragma unroll
    for (int i = 0; i < 4; i++) {
        int e = t + i * 256;
        cl[i] = e >> 5;
        pp[i] = e & 31;
    }

    // ---- issue half-0 LDGs (16 LDG.128) ----
    float4 q[4][4];
    #pragma unroll
    for (int i = 0; i < 4; i++) {
        int fbase = cl[i] * 524288 + d0 * 65536 + h0 * 256 + 2 * W0 + 4 * pp[i];
        int b4 = fbase >> 2;
        q[i][0] = sp4[b4];
        q[i][1] = sp4[b4 + 64];
        q[i][2] = sp4[b4 + 16384];
        q[i][3] = sp4[b4 + 16384 + 64];
    }

    // ---- stage conv_w + conv_b + sum (overlaps half-0 latency) ----
    {
        const float4* w4p = (const float4*)conv_w;
        float4*       s4p = (float4*)sh_w;
        #pragma unroll
        for (int i = t; i < 2048; i += 256) s4p[i] = w4p[i];
        if (t < 128) sh_b[t] = conv_b[t];
        if (t == 0) s_sum = g_hm[HM_CELLS];
    }

    // ---- average + STS half-0 ----
    #pragma unroll
    for (int i = 0; i < 4; i++) {
        float o0 = (q[i][0].x + q[i][0].y + q[i][1].x + q[i][1].y +
                    q[i][2].x + q[i][2].y + q[i][3].x + q[i][3].y) * 0.125f;
        float o1 = (q[i][0].z + q[i][0].w + q[i][1].z + q[i][1].w +
                    q[i][2].z + q[i][2].w + q[i][3].z + q[i][3].w) * 0.125f;
        *(float2*)&sh_avg[0][cl[i]][2 * pp[i]] = make_float2(o0, o1);
    }
    __syncthreads();

    int l  = t & 31;
    int og = t >> 5;
    int sp0 = D * 16384 + H * 128 + W0 + 2 * l;   // spatial index (D,H,W)

    // hm factor: load + consume now (before the zero later)
    float scale = 10.0f / (s_sum + 1e-4f);
    float2 hm2 = *(const float2*)&g_hm[sp0];
    float f0 = hm2.x * scale;
    float f1 = hm2.y * scale;

    // ---- issue half-1 LDGs (hidden by the half-0 FMA block below) ----
    #pragma unroll
    for (int i = 0; i < 4; i++) {
        int fbase = (32 + cl[i]) * 524288 + d0 * 65536 + h0 * 256
                  + 2 * W0 + 4 * pp[i];
        int b4 = fbase >> 2;
        q[i][0] = sp4[b4];
        q[i][1] = sp4[b4 + 64];
        q[i][2] = sp4[b4 + 16384];
        q[i][3] = sp4[b4 + 16384 + 64];
    }

    float acc0[16], acc1[16];
    #pragma unroll
    for (int k = 0; k < 16; k++) { acc0[k] = 0.0f; acc1[k] = 0.0f; }

    // ---- compute half-0 (c in [0,32)) ----
    #pragma unroll
    for (int c4 = 0; c4 < 32; c4 += 4) {
        float2 va = *(const float2*)&sh_avg[0][c4 + 0][2 * l];
        float2 vb = *(const float2*)&sh_avg[0][c4 + 1][2 * l];
        float2 vc = *(const float2*)&sh_avg[0][c4 + 2][2 * l];
        float2 vd = *(const float2*)&sh_avg[0][c4 + 3][2 * l];
        #pragma unroll
        for (int k = 0; k < 16; k++) {
            const float4 w4 = *(const float4*)&sh_w[(og * 16 + k) * 64 + c4];
            acc0[k] += w4.x * va.x + w4.y * vb.x + w4.z * vc.x + w4.w * vd.x;
            acc1[k] += w4.x * va.y + w4.y * vb.y + w4.z * vc.y + w4.w * vd.y;
        }
    }

    // ---- average + STS half-1 ----
    #pragma unroll
    for (int i = 0; i < 4; i++) {
        float o0 = (q[i][0].x + q[i][0].y + q[i][1].x + q[i][1].y +
                    q[i][2].x + q[i][2].y + q[i][3].x + q[i][3].y) * 0.125f;
        float o1 = (q[i][0].z + q[i][0].w + q[i][1].z + q[i][1].w +
                    q[i][2].z + q[i][2].w + q[i][3].z + q[i][3].w) * 0.125f;
        *(float2*)&sh_avg[1][cl[i]][2 * pp[i]] = make_float2(o0, o1);
    }
    __syncthreads();

    // self-clean: every warp consumed hm2 before this barrier
    if (og == 0)
        *(float2*)&g_hm[sp0] = make_float2(0.0f, 0.0f);
    if (t == 0) {
        int old = atomicAdd(&g_done, 1);
        if (old == (int)(gridDim.x * gridDim.y * gridDim.z) - 1) {
            g_hm[HM_CELLS] = 0.0f;   // all blocks have read the sum
            g_done = 0;
        }
    }

    // ---- compute half-1 (c in [32,64)) ----
    #pragma unroll
    for (int c4 = 32; c4 < 64; c4 += 4) {
        float2 va = *(const float2*)&sh_avg[1][c4 - 32 + 0][2 * l];
        float2 vb = *(const float2*)&sh_avg[1][c4 - 32 + 1][2 * l];
        float2 vc = *(const float2*)&sh_avg[1][c4 - 32 + 2][2 * l];
        float2 vd = *(const float2*)&sh_avg[1][c4 - 32 + 3][2 * l];
        #pragma unroll
        for (int k = 0; k < 16; k++) {
            const float4 w4 = *(const float4*)&sh_w[(og * 16 + k) * 64 + c4];
            acc0[k] += w4.x * va.x + w4.y * vb.x + w4.z * vc.x + w4.w * vd.x;
            acc1[k] += w4.x * va.y + w4.y * vb.y + w4.z * vc.y + w4.w * vd.y;
        }
    }

    // Epilogue: loss = |conv + b - teacher| * hm * 10 / (sum + 1e-4)
    #pragma unroll
    for (int k = 0; k < 16; k++) {
        int o   = og * 16 + k;
        int idx = o * 32768 + sp0;
        float2 t2 = *(const float2*)&teacher[idx];
        float  bk = sh_b[o];
        float2 r;
        r.x = fabsf(acc0[k] + bk - t2.x) * f0;
        r.y = fabsf(acc1[k] + bk - t2.y) * f1;
        *(float2*)&out[idx] = r;
    }
}

extern "C" void kernel_launch(void* const* d_in, const int* in_sizes, int n_in,
                              void* d_out, int out_size) {
    const float* boxes   = (const float*)d_in[0];
    // d_in[1] = gt_labels_3d (unused by reference)
    const float* teacher = (const float*)d_in[2];
    const float* student = (const float*)d_in[3];
    const float* conv_w  = (const float*)d_in[4];
    const float* conv_b  = (const float*)d_in[5];
    int N = in_sizes[0] / 9;

    if (N > 0) vd_scatter_kernel<<<N, 256>>>(boxes);

    dim3 grid(2, 128, 2);
    vd_main_kernel<<<grid, 256>>>(student, teacher, conv_w, conv_b,
                                  (float*)d_out);
}